// round 2
// baseline (speedup 1.0000x reference)
#include <cuda_runtime.h>
#include <math.h>

#define NN 100000          // nodes
#define NE 1600000         // edges (without self loops)
#define TE (NE + NN)       // edges + self loops
#define NG 512             // graphs

// ---------------- scratch (device globals; no runtime allocation) ----------
__device__ float    g_h1[NN * 32];      // layer1 features [N,2,16]
__device__ float    g_as1[NN * 2];
__device__ float    g_ad1[NN * 2];
__device__ unsigned g_m1[NN * 2];       // segment max (ordered-uint encoding)
__device__ float    g_den1[NN * 2];
__device__ float    g_w1[TE * 2];       // exp weights per edge
__device__ float    g_out1[NN * 32];

__device__ float    g_h2[NN * 32];
__device__ float    g_as2[NN];
__device__ float    g_ad2[NN];
__device__ unsigned g_m2[NN];
__device__ float    g_den2[NN];
__device__ float    g_w2[TE];
__device__ float    g_out2[NN * 32];

__device__ float    g_pool[NG * 32];

// order-preserving float<->uint mapping for atomicMax on floats
__device__ __forceinline__ unsigned f2o(float f) {
    unsigned u = __float_as_uint(f);
    return (u & 0x80000000u) ? ~u : (u | 0x80000000u);
}
__device__ __forceinline__ float o2f(unsigned u) {
    return (u & 0x80000000u) ? __uint_as_float(u & 0x7fffffffu) : __uint_as_float(~u);
}

__device__ __forceinline__ float lrelu(float x) { return x > 0.f ? x : 0.2f * x; }

// ---------------- init: zero all accumulators ------------------------------
__global__ void k_init() {
    int i = blockIdx.x * blockDim.x + threadIdx.x;
    int stride = gridDim.x * blockDim.x;
    for (int j = i; j < NN * 32; j += stride) { g_out1[j] = 0.f; g_out2[j] = 0.f; }
    for (int j = i; j < NN * 2;  j += stride) { g_m1[j] = 0u; g_den1[j] = 0.f; }
    for (int j = i; j < NN;      j += stride) { g_m2[j] = 0u; g_den2[j] = 0.f; }
    for (int j = i; j < NG * 32; j += stride) { g_pool[j] = 0.f; }
}

// ---------------- layer 1 node transform: h1 = x@W1, alpha_s/d -------------
// 256 threads = 8 nodes x 32 out-cols
__global__ void k_node1(const float* __restrict__ x, const float* __restrict__ W1,
                        const float* __restrict__ asw, const float* __restrict__ adw) {
    __shared__ float Ws[64 * 32];
    __shared__ float xs[8 * 64];
    int t = threadIdx.x;
    for (int i = t; i < 64 * 32; i += 256) Ws[i] = W1[i];
    int node0 = blockIdx.x * 8;
    for (int i = t; i < 512; i += 256) {
        int ln = i >> 6, k = i & 63;
        int n = node0 + ln;
        xs[i] = (n < NN) ? x[n * 64 + k] : 0.f;
    }
    __syncthreads();
    int ln = t >> 5, col = t & 31;
    int n = node0 + ln;
    if (n >= NN) return;
    float acc = 0.f;
#pragma unroll
    for (int k = 0; k < 64; k++) acc = fmaf(xs[ln * 64 + k], Ws[k * 32 + col], acc);
    g_h1[n * 32 + col] = acc;
    // per-head (16-lane) reductions for attention coefficients
    float ts = acc * asw[col];
    float td = acc * adw[col];
#pragma unroll
    for (int o = 1; o < 16; o <<= 1) {
        ts += __shfl_xor_sync(0xffffffffu, ts, o, 16);
        td += __shfl_xor_sync(0xffffffffu, td, o, 16);
    }
    if ((col & 15) == 0) {
        int head = col >> 4;
        g_as1[n * 2 + head] = ts;
        g_ad1[n * 2 + head] = td;
    }
}

// ---------------- layer 1 edge passes ---------------------------------------
__global__ void k_max1(const int* __restrict__ ei) {
    int i = blockIdx.x * blockDim.x + threadIdx.x;
    if (i >= TE) return;
    int s, d;
    if (i < NE) { s = ei[i]; d = ei[NE + i]; } else { s = d = i - NE; }
#pragma unroll
    for (int h = 0; h < 2; h++) {
        float e = lrelu(g_as1[s * 2 + h] + g_ad1[d * 2 + h]);
        atomicMax(&g_m1[d * 2 + h], f2o(e));
    }
}

__global__ void k_exp1(const int* __restrict__ ei) {
    int i = blockIdx.x * blockDim.x + threadIdx.x;
    if (i >= TE) return;
    int s, d;
    if (i < NE) { s = ei[i]; d = ei[NE + i]; } else { s = d = i - NE; }
#pragma unroll
    for (int h = 0; h < 2; h++) {
        float e = lrelu(g_as1[s * 2 + h] + g_ad1[d * 2 + h]);
        float m = o2f(g_m1[d * 2 + h]);
        float w = __expf(e - m);
        g_w1[i * 2 + h] = w;
        atomicAdd(&g_den1[d * 2 + h], w);
    }
}

// warp per edge, lane = output channel (head = lane/16)
__global__ void k_sc1(const int* __restrict__ ei) {
    int gid = blockIdx.x * blockDim.x + threadIdx.x;
    int e = gid >> 5;
    int lane = gid & 31;
    if (e >= TE) return;
    int s, d;
    if (e < NE) { s = ei[e]; d = ei[NE + e]; } else { s = d = e - NE; }
    int head = lane >> 4;
    float alpha = g_w1[e * 2 + head] / (g_den1[d * 2 + head] + 1e-16f);
    atomicAdd(&g_out1[d * 32 + lane], g_h1[s * 32 + lane] * alpha);
}

// ---------------- layer 2 node transform ------------------------------------
__global__ void k_node2(const float* __restrict__ W2, const float* __restrict__ b1,
                        const float* __restrict__ asw, const float* __restrict__ adw) {
    __shared__ float Ws[32 * 32];
    __shared__ float xs[8 * 32];
    int t = threadIdx.x;
    for (int i = t; i < 32 * 32; i += 256) Ws[i] = W2[i];
    int node0 = blockIdx.x * 8;
    {
        int ln = t >> 5, k = t & 31;
        int n = node0 + ln;
        float v = (n < NN) ? g_out1[n * 32 + k] + b1[k] : 0.f;
        xs[t] = v > 0.f ? v : 0.f;   // ReLU between layers
    }
    __syncthreads();
    int ln = t >> 5, col = t & 31;
    int n = node0 + ln;
    if (n >= NN) return;
    float acc = 0.f;
#pragma unroll
    for (int k = 0; k < 32; k++) acc = fmaf(xs[ln * 32 + k], Ws[k * 32 + col], acc);
    g_h2[n * 32 + col] = acc;
    float ts = acc * asw[col];
    float td = acc * adw[col];
#pragma unroll
    for (int o = 1; o < 32; o <<= 1) {
        ts += __shfl_xor_sync(0xffffffffu, ts, o);
        td += __shfl_xor_sync(0xffffffffu, td, o);
    }
    if (col == 0) { g_as2[n] = ts; g_ad2[n] = td; }
}

// ---------------- layer 2 edge passes ----------------------------------------
__global__ void k_max2(const int* __restrict__ ei) {
    int i = blockIdx.x * blockDim.x + threadIdx.x;
    if (i >= TE) return;
    int s, d;
    if (i < NE) { s = ei[i]; d = ei[NE + i]; } else { s = d = i - NE; }
    float e = lrelu(g_as2[s] + g_ad2[d]);
    atomicMax(&g_m2[d], f2o(e));
}

__global__ void k_exp2(const int* __restrict__ ei) {
    int i = blockIdx.x * blockDim.x + threadIdx.x;
    if (i >= TE) return;
    int s, d;
    if (i < NE) { s = ei[i]; d = ei[NE + i]; } else { s = d = i - NE; }
    float e = lrelu(g_as2[s] + g_ad2[d]);
    float m = o2f(g_m2[d]);
    float w = __expf(e - m);
    g_w2[i] = w;
    atomicAdd(&g_den2[d], w);
}

__global__ void k_sc2(const int* __restrict__ ei) {
    int gid = blockIdx.x * blockDim.x + threadIdx.x;
    int e = gid >> 5;
    int lane = gid & 31;
    if (e >= TE) return;
    int s, d;
    if (e < NE) { s = ei[e]; d = ei[NE + e]; } else { s = d = e - NE; }
    float alpha = g_w2[e] / (g_den2[d] + 1e-16f);
    atomicAdd(&g_out2[d * 32 + lane], g_h2[s * 32 + lane] * alpha);
}

// ---------------- pooling -----------------------------------------------------
__global__ void k_pool(const int* __restrict__ batch, const float* __restrict__ b2) {
    int i = blockIdx.x * blockDim.x + threadIdx.x;
    if (i >= NN * 32) return;
    int n = i >> 5, c = i & 31;
    float v = g_out2[i] + b2[c];
    v = v > 0.f ? v : 0.f;
    atomicAdd(&g_pool[batch[n] * 32 + c], v);
}

// ---------------- MLP head + sigmoid ------------------------------------------
__global__ void k_head(const float* __restrict__ lw1, const float* __restrict__ lb1,
                       const float* __restrict__ lw2, const float* __restrict__ lb2,
                       float* __restrict__ out) {
    __shared__ float p[32];
    __shared__ float tbuf[64];
    int g = blockIdx.x;
    int t = threadIdx.x;  // 64 threads
    if (t < 32) p[t] = g_pool[g * 32 + t];
    __syncthreads();
    float acc = lb1[t];
#pragma unroll
    for (int k = 0; k < 32; k++) acc = fmaf(p[k], lw1[k * 64 + t], acc);
    tbuf[t] = acc > 0.f ? acc : 0.f;
    __syncthreads();
    if (t < 2) {
        float o = lb2[t];
#pragma unroll
        for (int j = 0; j < 64; j++) o = fmaf(tbuf[j], lw2[j * 2 + t], o);
        out[g * 2 + t] = 1.f / (1.f + expf(-o));
    }
}

// ---------------- launch -------------------------------------------------------
extern "C" void kernel_launch(void* const* d_in, const int* in_sizes, int n_in,
                              void* d_out, int out_size) {
    const float* x    = (const float*)d_in[0];
    const int*   ei   = (const int*)d_in[1];
    const int*   batch= (const int*)d_in[2];
    const float* W1   = (const float*)d_in[3];
    const float* as1  = (const float*)d_in[4];
    const float* ad1  = (const float*)d_in[5];
    const float* b1   = (const float*)d_in[6];
    const float* W2   = (const float*)d_in[7];
    const float* as2  = (const float*)d_in[8];
    const float* ad2  = (const float*)d_in[9];
    const float* b2   = (const float*)d_in[10];
    const float* lw1  = (const float*)d_in[11];
    const float* lb1  = (const float*)d_in[12];
    const float* lw2  = (const float*)d_in[13];
    const float* lb2  = (const float*)d_in[14];
    float* out = (float*)d_out;

    k_init<<<1024, 256>>>();

    // layer 1
    k_node1<<<(NN + 7) / 8, 256>>>(x, W1, as1, ad1);
    k_max1<<<(TE + 255) / 256, 256>>>(ei);
    k_exp1<<<(TE + 255) / 256, 256>>>(ei);
    k_sc1<<<(TE * 32 + 255) / 256, 256>>>(ei);

    // layer 2
    k_node2<<<(NN + 7) / 8, 256>>>(W2, b1, as2, ad2);
    k_max2<<<(TE + 255) / 256, 256>>>(ei);
    k_exp2<<<(TE + 255) / 256, 256>>>(ei);
    k_sc2<<<(TE * 32 + 255) / 256, 256>>>(ei);

    // pool + head
    k_pool<<<(NN * 32 + 255) / 256, 256>>>(batch, b2);
    k_head<<<NG, 64>>>(lw1, lb1, lw2, lb2, out);
}

// round 3
// speedup vs baseline: 1.4451x; 1.4451x over previous
#include <cuda_runtime.h>
#include <math.h>

#define NN 100000          // nodes
#define NE 1600000         // edges (without self loops)
#define TE (NE + NN)       // edges + self loops
#define NG 512             // graphs

// ---------------- scratch (device globals) ---------------------------------
__device__ float g_h1[NN * 32];      // layer1 transformed features [N,2,16]
__device__ float g_as1[NN * 2];
__device__ float g_ad1[NN * 2];
__device__ float g_out1[NN * 32];

__device__ float g_h2[NN * 32];
__device__ float g_as2[NN];
__device__ float g_ad2[NN];
__device__ float g_out2[NN * 32];

__device__ int   g_deg[NN];
__device__ int   g_off[NN + 1];
__device__ int   g_cur[NN];
__device__ int   g_adj[TE];          // src node per incoming edge, grouped by dst

__device__ float g_pool[NG * 32];

__device__ __forceinline__ float lrelu(float x) { return x > 0.f ? x : 0.2f * x; }

// ---------------- init: zero counters --------------------------------------
__global__ void k_init() {
    int i = blockIdx.x * blockDim.x + threadIdx.x;
    int stride = gridDim.x * blockDim.x;
    for (int j = i; j < NN; j += stride) g_deg[j] = 0;
    for (int j = i; j < NG * 32; j += stride) g_pool[j] = 0.f;
}

// ---------------- CSR build -------------------------------------------------
__global__ void k_count(const int* __restrict__ ei) {
    int i = blockIdx.x * blockDim.x + threadIdx.x;
    if (i >= TE) return;
    int d = (i < NE) ? ei[NE + i] : (i - NE);
    atomicAdd(&g_deg[d], 1);
}

#define SCAN_T 1024
#define SCAN_C ((NN + SCAN_T - 1) / SCAN_T)   // 98 elements per thread

__global__ void k_scan() {
    __shared__ int sums[SCAN_T];
    int t = threadIdx.x;
    int base = t * SCAN_C;
    int local = 0;
    for (int i = 0; i < SCAN_C; i++) {
        int idx = base + i;
        if (idx < NN) local += g_deg[idx];
    }
    sums[t] = local;
    __syncthreads();
    for (int off = 1; off < SCAN_T; off <<= 1) {
        int v = (t >= off) ? sums[t - off] : 0;
        __syncthreads();
        sums[t] += v;
        __syncthreads();
    }
    int run = (t == 0) ? 0 : sums[t - 1];
    for (int i = 0; i < SCAN_C; i++) {
        int idx = base + i;
        if (idx < NN) {
            g_off[idx] = run;
            g_cur[idx] = run;
            run += g_deg[idx];
        }
    }
    if (t == SCAN_T - 1) g_off[NN] = run;
}

__global__ void k_place(const int* __restrict__ ei) {
    int i = blockIdx.x * blockDim.x + threadIdx.x;
    if (i >= TE) return;
    int s, d;
    if (i < NE) { s = ei[i]; d = ei[NE + i]; } else { s = d = i - NE; }
    int slot = atomicAdd(&g_cur[d], 1);
    g_adj[slot] = s;
}

// ---------------- layer 1 node transform ------------------------------------
__global__ void k_node1(const float* __restrict__ x, const float* __restrict__ W1,
                        const float* __restrict__ asw, const float* __restrict__ adw) {
    __shared__ float Ws[64 * 32];
    __shared__ float xs[8 * 64];
    int t = threadIdx.x;
    for (int i = t; i < 64 * 32; i += 256) Ws[i] = W1[i];
    int node0 = blockIdx.x * 8;
    for (int i = t; i < 512; i += 256) {
        int ln = i >> 6, k = i & 63;
        int n = node0 + ln;
        xs[i] = (n < NN) ? x[n * 64 + k] : 0.f;
    }
    __syncthreads();
    int ln = t >> 5, col = t & 31;
    int n = node0 + ln;
    if (n >= NN) return;
    float acc = 0.f;
#pragma unroll
    for (int k = 0; k < 64; k++) acc = fmaf(xs[ln * 64 + k], Ws[k * 32 + col], acc);
    g_h1[n * 32 + col] = acc;
    float ts = acc * asw[col];
    float td = acc * adw[col];
#pragma unroll
    for (int o = 1; o < 16; o <<= 1) {
        ts += __shfl_xor_sync(0xffffffffu, ts, o, 16);
        td += __shfl_xor_sync(0xffffffffu, td, o, 16);
    }
    if ((col & 15) == 0) {
        int head = col >> 4;
        g_as1[n * 2 + head] = ts;
        g_ad1[n * 2 + head] = td;
    }
}

// ---------------- layer 1 fused softmax-aggregate (warp per dst node) --------
__global__ void k_agg1() {
    int w = (blockIdx.x * blockDim.x + threadIdx.x) >> 5;
    int lane = threadIdx.x & 31;
    if (w >= NN) return;
    int o0 = g_off[w], o1 = g_off[w + 1];
    int head = lane >> 4;
    float ad = g_ad1[w * 2 + head];
    float acc = 0.f, den = 0.f;
    for (int k = o0; k < o1; k++) {
        int s = g_adj[k];
        float wt = __expf(lrelu(g_as1[s * 2 + head] + ad));
        den += wt;
        acc += wt * g_h1[s * 32 + lane];
    }
    g_out1[w * 32 + lane] = acc / (den + 1e-16f);
}

// ---------------- layer 2 node transform ------------------------------------
__global__ void k_node2(const float* __restrict__ W2, const float* __restrict__ b1,
                        const float* __restrict__ asw, const float* __restrict__ adw) {
    __shared__ float Ws[32 * 32];
    __shared__ float xs[8 * 32];
    int t = threadIdx.x;
    for (int i = t; i < 32 * 32; i += 256) Ws[i] = W2[i];
    int node0 = blockIdx.x * 8;
    {
        int ln = t >> 5, k = t & 31;
        int n = node0 + ln;
        float v = (n < NN) ? g_out1[n * 32 + k] + b1[k] : 0.f;
        xs[t] = v > 0.f ? v : 0.f;
    }
    __syncthreads();
    int ln = t >> 5, col = t & 31;
    int n = node0 + ln;
    if (n >= NN) return;
    float acc = 0.f;
#pragma unroll
    for (int k = 0; k < 32; k++) acc = fmaf(xs[ln * 32 + k], Ws[k * 32 + col], acc);
    g_h2[n * 32 + col] = acc;
    float ts = acc * asw[col];
    float td = acc * adw[col];
#pragma unroll
    for (int o = 1; o < 32; o <<= 1) {
        ts += __shfl_xor_sync(0xffffffffu, ts, o);
        td += __shfl_xor_sync(0xffffffffu, td, o);
    }
    if (col == 0) { g_as2[n] = ts; g_ad2[n] = td; }
}

// ---------------- layer 2 fused softmax-aggregate ----------------------------
__global__ void k_agg2() {
    int w = (blockIdx.x * blockDim.x + threadIdx.x) >> 5;
    int lane = threadIdx.x & 31;
    if (w >= NN) return;
    int o0 = g_off[w], o1 = g_off[w + 1];
    float ad = g_ad2[w];
    float acc = 0.f, den = 0.f;
    for (int k = o0; k < o1; k++) {
        int s = g_adj[k];
        float wt = __expf(lrelu(g_as2[s] + ad));
        den += wt;
        acc += wt * g_h2[s * 32 + lane];
    }
    g_out2[w * 32 + lane] = acc / (den + 1e-16f);
}

// ---------------- pooling (batch is sorted: register accumulate, flush) ------
__global__ void k_pool(const int* __restrict__ batch, const float* __restrict__ b2) {
    int w = (blockIdx.x * blockDim.x + threadIdx.x) >> 5;   // warp handles 8 nodes
    int lane = threadIdx.x & 31;
    int n0 = w * 8;
    if (n0 >= NN) return;
    float bb = b2[lane];
    float acc = 0.f;
    int cur = batch[n0];
#pragma unroll
    for (int j = 0; j < 8; j++) {
        int n = n0 + j;
        if (n >= NN) break;
        int b = batch[n];
        if (b != cur) {
            atomicAdd(&g_pool[cur * 32 + lane], acc);
            acc = 0.f;
            cur = b;
        }
        float v = g_out2[n * 32 + lane] + bb;
        acc += v > 0.f ? v : 0.f;
    }
    atomicAdd(&g_pool[cur * 32 + lane], acc);
}

// ---------------- MLP head + sigmoid ------------------------------------------
__global__ void k_head(const float* __restrict__ lw1, const float* __restrict__ lb1,
                       const float* __restrict__ lw2, const float* __restrict__ lb2,
                       float* __restrict__ out) {
    __shared__ float p[32];
    __shared__ float tbuf[64];
    int g = blockIdx.x;
    int t = threadIdx.x;  // 64 threads
    if (t < 32) p[t] = g_pool[g * 32 + t];
    __syncthreads();
    float acc = lb1[t];
#pragma unroll
    for (int k = 0; k < 32; k++) acc = fmaf(p[k], lw1[k * 64 + t], acc);
    tbuf[t] = acc > 0.f ? acc : 0.f;
    __syncthreads();
    if (t < 2) {
        float o = lb2[t];
#pragma unroll
        for (int j = 0; j < 64; j++) o = fmaf(tbuf[j], lw2[j * 2 + t], o);
        out[g * 2 + t] = 1.f / (1.f + expf(-o));
    }
}

// ---------------- launch -------------------------------------------------------
extern "C" void kernel_launch(void* const* d_in, const int* in_sizes, int n_in,
                              void* d_out, int out_size) {
    const float* x    = (const float*)d_in[0];
    const int*   ei   = (const int*)d_in[1];
    const int*   batch= (const int*)d_in[2];
    const float* W1   = (const float*)d_in[3];
    const float* as1  = (const float*)d_in[4];
    const float* ad1  = (const float*)d_in[5];
    const float* b1   = (const float*)d_in[6];
    const float* W2   = (const float*)d_in[7];
    const float* as2  = (const float*)d_in[8];
    const float* ad2  = (const float*)d_in[9];
    const float* b2   = (const float*)d_in[10];
    const float* lw1  = (const float*)d_in[11];
    const float* lb1  = (const float*)d_in[12];
    const float* lw2  = (const float*)d_in[13];
    const float* lb2  = (const float*)d_in[14];
    float* out = (float*)d_out;

    k_init<<<512, 256>>>();

    // CSR build (shared by both layers)
    k_count<<<(TE + 255) / 256, 256>>>(ei);
    k_scan<<<1, SCAN_T>>>();
    k_place<<<(TE + 255) / 256, 256>>>(ei);

    // layer 1
    k_node1<<<(NN + 7) / 8, 256>>>(x, W1, as1, ad1);
    k_agg1<<<(NN * 32 + 255) / 256, 256>>>();

    // layer 2
    k_node2<<<(NN + 7) / 8, 256>>>(W2, b1, as2, ad2);
    k_agg2<<<(NN * 32 + 255) / 256, 256>>>();

    // pool + head
    k_pool<<<(NN / 8) * 32 / 256 + 1, 256>>>(batch, b2);
    k_head<<<NG, 64>>>(lw1, lb1, lw2, lb2, out);
}